// round 5
// baseline (speedup 1.0000x reference)
#include <cuda_runtime.h>
#include <math.h>

#define IMG 256
#define NJ 21
#define NB 64
#define NIMG (NB * NJ)          // 1344
#define IMG_ELEMS (IMG * IMG)   // 65536

// ---------------------------------------------------------------------------
// Kernel 1: blank the entire output with vectorized stores (write-bound).
// ---------------------------------------------------------------------------
__global__ void __launch_bounds__(256) zero_kernel(float4* __restrict__ out, int n4) {
    int i = blockIdx.x * blockDim.x + threadIdx.x;
    int stride = gridDim.x * blockDim.x;
    const float4 z = make_float4(0.f, 0.f, 0.f, 0.f);
    for (; i < n4; i += stride) out[i] = z;
}

// ---------------------------------------------------------------------------
// Kernel 2: one block per (b, j) image. Compute fisheye (u,v), stamp the
// truncated 11x11 peak-to-one gaussian. Runs after zero_kernel in stream
// order, so it just overwrites 121 (or fewer) pixels.
// ---------------------------------------------------------------------------
__global__ void __launch_bounds__(128) stamp_kernel(const float* __restrict__ joint,
                                                    float* __restrict__ out) {
    const int img = blockIdx.x;            // 0 .. 1343  == b*21 + j
    const int t = threadIdx.x;             // 0 .. 127

    // every thread redundantly computes the projection (3 loads, cheap)
    const float x = joint[img * 3 + 0];
    const float y = joint[img * 3 + 1];
    const float z = joint[img * 3 + 2];

    const float theta = atan2f(sqrtf(x * x + y * y), z);
    const float phi   = atan2f(y, x);
    const float r     = (128.0f * theta) / 1.5707963267948966f;  // RADIUS*theta/(pi/2)

    // jnp.round == round-half-to-even == rintf
    int cx = (int)rintf(128.0f + r * cosf(phi));
    int cy = (int)rintf(128.0f + r * sinf(phi));
    cx = min(max(cx, 0), IMG - 1);
    cy = min(max(cy, 0), IMG - 1);

    if (t < 121) {
        const int dy = t / 11 - 5;
        const int dx = t % 11 - 5;
        const int px = cx + dx;
        const int py = cy + dy;
        if (px >= 0 && px < IMG && py >= 0 && py < IMG) {
            // peak-to-one gaussian: exp(-(dx^2+dy^2) / (2 * 2.5^2))
            const float w = expf(-(float)(dx * dx + dy * dy) * (1.0f / 12.5f));
            out[(long long)img * IMG_ELEMS + py * IMG + px] = w;
        }
    }
}

extern "C" void kernel_launch(void* const* d_in, const int* in_sizes, int n_in,
                              void* d_out, int out_size) {
    const float* joint = (const float*)d_in[0];   // [64, 21, 3] f32
    float* out = (float*)d_out;                   // [64, 21, 256, 256] f32

    const int n4 = out_size / 4;                  // 22,020,096 float4
    // full-chip write stream: 148 SMs * 16 blocks, 256 threads, grid-stride
    zero_kernel<<<148 * 16, 256>>>((float4*)out, n4);
    stamp_kernel<<<NIMG, 128>>>(joint, out);
}

// round 9
// speedup vs baseline: 1.1648x; 1.1648x over previous
#include <cuda_runtime.h>
#include <math.h>

#define IMG 256
#define NJ 21
#define NB 64
#define NIMG (NB * NJ)              // 1344
#define IMG_ELEMS (IMG * IMG)       // 65536
#define F4_PER_IMG (IMG_ELEMS / 4)  // 16384
#define BLOCKS_PER_IMG 16           // 16 rows per block
#define F4_PER_BLOCK (F4_PER_IMG / BLOCKS_PER_IMG)  // 1024

// ---------------------------------------------------------------------------
// Fused kernel: each block owns a 16-row slab of one (b, j) image.
// It computes the fisheye projection for that image (redundantly per thread;
// cheap MUFU work hidden behind the store stream) and writes the slab:
// zeros everywhere except the truncated 11x11 peak-to-one gaussian stamp.
// Single pass over the 352 MB output -> pure write-stream, DRAM-bound.
// ---------------------------------------------------------------------------
__global__ void __launch_bounds__(256) fused_kernel(const float* __restrict__ joint,
                                                    float4* __restrict__ out4) {
    const int blk = blockIdx.x;
    const int img = blk >> 4;                       // blk / BLOCKS_PER_IMG
    const int rowbase = (blk & 15) << 4;            // (blk % 16) * 16

    // fisheye projection for this image
    const float x = joint[img * 3 + 0];
    const float y = joint[img * 3 + 1];
    const float z = joint[img * 3 + 2];

    const float theta = atan2f(sqrtf(x * x + y * y), z);
    const float phi   = atan2f(y, x);
    const float r     = (128.0f * theta) / 1.5707963267948966f;  // RADIUS*theta/(pi/2)

    // jnp.round == round-half-to-even == rintf
    int cx = (int)rintf(128.0f + r * cosf(phi));
    int cy = (int)rintf(128.0f + r * sinf(phi));
    cx = min(max(cx, 0), IMG - 1);
    cy = min(max(cy, 0), IMG - 1);

    float4* __restrict__ base = out4 + (size_t)img * F4_PER_IMG + (size_t)rowbase * (IMG / 4);
    const int t = threadIdx.x;
    const float4 zero4 = make_float4(0.f, 0.f, 0.f, 0.f);

    #pragma unroll
    for (int k = 0; k < 4; k++) {
        const int idx  = t + k * 256;               // 0 .. 1023 within slab
        const int row  = rowbase + (idx >> 6);      // 64 float4 per row
        const int col4 = (idx & 63) << 2;           // starting column of this float4

        float4 v = zero4;
        const int dy = row - cy;
        if (dy >= -5 && dy <= 5) {
            #pragma unroll
            for (int c = 0; c < 4; c++) {
                const int dx = col4 + c - cx;
                if (dx >= -5 && dx <= 5) {
                    // peak-to-one gaussian: exp(-(dx^2+dy^2) / (2 * 2.5^2))
                    ((float*)&v)[c] = expf(-(float)(dx * dx + dy * dy) * (1.0f / 12.5f));
                }
            }
        }
        base[idx] = v;
    }
}

extern "C" void kernel_launch(void* const* d_in, const int* in_sizes, int n_in,
                              void* d_out, int out_size) {
    const float* joint = (const float*)d_in[0];   // [64, 21, 3] f32
    float* out = (float*)d_out;                   // [64, 21, 256, 256] f32

    fused_kernel<<<NIMG * BLOCKS_PER_IMG, 256>>>(joint, (float4*)out);
}

// round 12
// speedup vs baseline: 1.1735x; 1.0075x over previous
#include <cuda_runtime.h>
#include <math.h>

#define IMG 256
#define NJ 21
#define NB 64
#define NIMG (NB * NJ)              // 1344
#define IMG_ELEMS (IMG * IMG)       // 65536
#define F4_PER_IMG (IMG_ELEMS / 4)  // 16384
#define BLOCKS_PER_IMG 16           // 16 rows per block
#define F4_PER_BLOCK (F4_PER_IMG / BLOCKS_PER_IMG)  // 1024

// ---------------------------------------------------------------------------
// Fused kernel: each block owns a 16-row slab of one (b, j) image.
// Block-uniform fast path: if the 11-row gaussian stamp window does not
// intersect this slab (~88% of blocks), do a straight-line streaming
// zero-fill with no per-element math. Otherwise take the predicated
// gaussian-stamp path. Single pass over the 352 MB output.
// ---------------------------------------------------------------------------
__global__ void __launch_bounds__(256) fused_kernel(const float* __restrict__ joint,
                                                    float4* __restrict__ out4) {
    const int blk = blockIdx.x;
    const int img = blk >> 4;                       // blk / BLOCKS_PER_IMG
    const int rowbase = (blk & 15) << 4;            // (blk % 16) * 16

    // fisheye projection for this image (redundant per thread; cheap)
    const float x = joint[img * 3 + 0];
    const float y = joint[img * 3 + 1];
    const float z = joint[img * 3 + 2];

    const float theta = atan2f(sqrtf(x * x + y * y), z);
    const float phi   = atan2f(y, x);
    const float r     = (128.0f * theta) / 1.5707963267948966f;  // RADIUS*theta/(pi/2)

    // jnp.round == round-half-to-even == rintf
    int cx = (int)rintf(128.0f + r * cosf(phi));
    int cy = (int)rintf(128.0f + r * sinf(phi));
    cx = min(max(cx, 0), IMG - 1);
    cy = min(max(cy, 0), IMG - 1);

    float4* __restrict__ base = out4 + (size_t)img * F4_PER_IMG + (size_t)rowbase * (IMG / 4);
    const int t = threadIdx.x;
    const float4 zero4 = make_float4(0.f, 0.f, 0.f, 0.f);

    // Does the stamp's row window [cy-5, cy+5] intersect this 16-row slab?
    // Uniform across the block -> no divergence.
    const bool touches = (rowbase <= cy + 5) && (rowbase + 15 >= cy - 5);

    if (!touches) {
        // ---- fast path: pure streaming zero-fill, no per-element math ----
        float4* p = base + t;
        __stcs(p,       zero4);
        __stcs(p + 256, zero4);
        __stcs(p + 512, zero4);
        __stcs(p + 768, zero4);
        return;
    }

    // ---- slow path: slab contains (part of) the gaussian stamp ----
    #pragma unroll
    for (int k = 0; k < 4; k++) {
        const int idx  = t + k * 256;               // 0 .. 1023 within slab
        const int row  = rowbase + (idx >> 6);      // 64 float4 per row
        const int col4 = (idx & 63) << 2;           // starting column of this float4

        float4 v = zero4;
        const int dy = row - cy;
        if (dy >= -5 && dy <= 5) {
            #pragma unroll
            for (int c = 0; c < 4; c++) {
                const int dx = col4 + c - cx;
                if (dx >= -5 && dx <= 5) {
                    // peak-to-one gaussian: exp(-(dx^2+dy^2) / (2 * 2.5^2))
                    ((float*)&v)[c] = expf(-(float)(dx * dx + dy * dy) * (1.0f / 12.5f));
                }
            }
        }
        __stcs(base + idx, v);
    }
}

extern "C" void kernel_launch(void* const* d_in, const int* in_sizes, int n_in,
                              void* d_out, int out_size) {
    const float* joint = (const float*)d_in[0];   // [64, 21, 3] f32
    float* out = (float*)d_out;                   // [64, 21, 256, 256] f32

    fused_kernel<<<NIMG * BLOCKS_PER_IMG, 256>>>(joint, (float4*)out);
}